// round 9
// baseline (speedup 1.0000x reference)
#include <cuda_runtime.h>
#include <cuda_bf16.h>
#include <math.h>
#include <stdint.h>
#include <stddef.h>

// ------------ problem constants ------------
#define Bsz   2048
#define Nn    20
#define Dd    512
#define Hh    8
#define Mrows (Bsz*Nn)     // 40960
#define K3    (3*Dd)       // 1536

// ------------ scratch (static __device__) ------------
__device__ __align__(256) float g_conv[(size_t)Mrows * K3];        // conv GEMM out (fp32)
__device__ __align__(256) float g_qp[(size_t)Mrows * Hh];
__device__ __align__(256) float g_wqft[(size_t)64 * Dd];           // Wqf^T [c][i]
__device__ __align__(256) __nv_bfloat16 g_xh[(size_t)Mrows * Dd];  // x split hi/lo
__device__ __align__(256) __nv_bfloat16 g_xl[(size_t)Mrows * Dd];
__device__ __align__(256) __nv_bfloat16 g_ah[(size_t)Mrows * Dd];  // attn out split
__device__ __align__(256) __nv_bfloat16 g_al[(size_t)Mrows * Dd];
__device__ __align__(256) __nv_bfloat16 g_wth[(size_t)K3 * K3];    // W^T concat [oc][kk]
__device__ __align__(256) __nv_bfloat16 g_wtl[(size_t)K3 * K3];
__device__ __align__(256) __nv_bfloat16 g_woh[(size_t)Dd * Dd];    // Wo^T [n][k]
__device__ __align__(256) __nv_bfloat16 g_wol[(size_t)Dd * Dd];

// ------------ small PTX helpers (plain-sm_103-safe) ------------
__device__ __forceinline__ uint32_t smem_u32(const void* p) {
    uint32_t a;
    asm("{ .reg .u64 t; cvta.to.shared.u64 t, %1; cvt.u32.u64 %0, t; }" : "=r"(a) : "l"(p));
    return a;
}
__device__ __forceinline__ void cp_async16(uint32_t saddr, const void* gaddr, uint32_t srcsize) {
    asm volatile("cp.async.cg.shared.global [%0], [%1], 16, %2;"
                 :: "r"(saddr), "l"(gaddr), "r"(srcsize) : "memory");
}
__device__ __forceinline__ void cp_commit() { asm volatile("cp.async.commit_group;" ::: "memory"); }
__device__ __forceinline__ void cp_wait0()  { asm volatile("cp.async.wait_group 0;" ::: "memory"); }

__device__ __forceinline__ void ldsm4(uint32_t* r, uint32_t addr) {
    asm volatile("ldmatrix.sync.aligned.m8n8.x4.shared.b16 {%0,%1,%2,%3}, [%4];"
                 : "=r"(r[0]), "=r"(r[1]), "=r"(r[2]), "=r"(r[3]) : "r"(addr));
}
__device__ __forceinline__ void mma16816(float* c, const uint32_t* a, const uint32_t* b) {
    asm volatile("mma.sync.aligned.m16n8k16.row.col.f32.bf16.bf16.f32 "
                 "{%0,%1,%2,%3}, {%4,%5,%6,%7}, {%8,%9}, {%0,%1,%2,%3};"
                 : "+f"(c[0]), "+f"(c[1]), "+f"(c[2]), "+f"(c[3])
                 : "r"(a[0]), "r"(a[1]), "r"(a[2]), "r"(a[3]), "r"(b[0]), "r"(b[1]));
}

// ============================================================
// precompute kernels
// ============================================================
__global__ void split_x(const float* __restrict__ x) {
    size_t i = (size_t)blockIdx.x * 256 + threadIdx.x;
    if (i >= (size_t)Mrows * Dd) return;
    float v = x[i];
    __nv_bfloat16 h = __float2bfloat16(v);
    g_xh[i] = h;
    g_xl[i] = __float2bfloat16(v - __bfloat162float(h));
}

__global__ void repack_w(const float* __restrict__ Wq,
                         const float* __restrict__ Wk,
                         const float* __restrict__ Wv) {
    size_t idx = (size_t)blockIdx.x * 256 + threadIdx.x;
    if (idx >= (size_t)K3 * K3) return;
    int oc = (int)(idx / K3);
    int kk = (int)(idx - (size_t)oc * K3);
    int t = kk >> 9, i = kk & 511;
    int p = oc >> 9, o = oc & 511;
    const float* W = (p == 0) ? Wq : (p == 1) ? Wk : Wv;
    float v = W[(size_t)o * K3 + i * 3 + t];
    __nv_bfloat16 h = __float2bfloat16(v);
    g_wth[idx] = h;
    g_wtl[idx] = __float2bfloat16(v - __bfloat162float(h));
}

__global__ void repack_wo(const float* __restrict__ Wo, const float* __restrict__ Wqf) {
    int idx = blockIdx.x * 256 + threadIdx.x;
    if (idx < 64 * Dd) {
        // Wqf^T: [c][i] = Wqf[i][c]
        int c = idx >> 9, i = idx & 511;
        g_wqft[idx] = Wqf[(size_t)i * 64 + c];
    }
    if (idx >= Dd * Dd) return;
    int n = idx >> 9, k = idx & 511;
    float v = Wo[(size_t)k * Dd + n];
    __nv_bfloat16 h = __float2bfloat16(v);
    g_woh[idx] = h;
    g_wol[idx] = __float2bfloat16(v - __bfloat162float(h));
}

// ============================================================
// warp-mma bf16 GEMM: C = A * B^T (B stored [N x K]); bf16x3 split.
// MODE 1: A gathered via im2col of x.
// CTA 128x128, 256 thr (8 warps, 2x4), warp tile 64x32, BK=32,
// double buffer, SINGLE __syncthreads per K-iter:
//   wait(stage c) -> barrier -> issue load(c+1) -> MMA(stage c)
// Safe because load(c+1) writes buf (c+1)&1, last read at iter c-1,
// and the barrier guarantees all warps finished iter c-1.
// 2 CTAs/SM via __launch_bounds__(256,2).
// ============================================================
#define LDS_E 40
#define TILE_E (128 * LDS_E)
#define TILE_BYTES (TILE_E * 2)          // 10240 B
#define STAGE_BYTES (4 * TILE_BYTES)     // 40960 B
#define GEMM_SMEM (2 * STAGE_BYTES)      // 81920 B

template<int MODE, bool BIAS>
__global__ __launch_bounds__(256, 2)
void tc_gemm(const __nv_bfloat16* __restrict__ Ah, const __nv_bfloat16* __restrict__ Al,
             const __nv_bfloat16* __restrict__ Bh, const __nv_bfloat16* __restrict__ Bl,
             float* __restrict__ C, const float* __restrict__ bias, int K, int N)
{
    extern __shared__ __nv_bfloat16 smem[];
    const uint32_t sb = smem_u32(smem);
    const int tid = threadIdx.x;
    const int wid = tid >> 5, lid = tid & 31;
    const int warp_m = wid >> 2;      // 0..1  (64 rows)
    const int warp_n = wid & 3;       // 0..3  (32 cols)
    const int m0 = blockIdx.y * 128, n0 = blockIdx.x * 128;
    const int NC = K >> 5;

    auto load_stage = [&](int c) {
        const int buf = c & 1;
        const int kk0 = c << 5;
        uint32_t sbase = sb + (uint32_t)buf * STAGE_BYTES;
        #pragma unroll
        for (int it = 0; it < 2; it++) {
            int id = tid + it * 256;            // 0..511
            int r = id >> 2, q = id & 3;        // row, 16B quad
            uint32_t soff = (uint32_t)(r * LDS_E + q * 8) * 2;
            size_t aoff; uint32_t vsz = 16;
            if (MODE == 1) {
                int gm = m0 + r;
                int bb = gm / Nn, nn = gm - bb * Nn;
                int t = kk0 >> 9;
                int d = (kk0 & 511) + q * 8;
                int jj = nn + t - 1;
                if (jj < 0 || jj >= Nn) { vsz = 0; jj = 0; }
                aoff = ((size_t)(bb * Nn + jj) << 9) + d;
            } else {
                aoff = (size_t)(m0 + r) * K + kk0 + q * 8;
            }
            cp_async16(sbase + 0 * TILE_BYTES + soff, Ah + aoff, vsz);
            cp_async16(sbase + 1 * TILE_BYTES + soff, Al + aoff, vsz);
            size_t boff = (size_t)(n0 + r) * K + kk0 + q * 8;
            cp_async16(sbase + 2 * TILE_BYTES + soff, Bh + boff, 16);
            cp_async16(sbase + 3 * TILE_BYTES + soff, Bl + boff, 16);
        }
        cp_commit();
    };

    float acc[4][4][4];
    #pragma unroll
    for (int i = 0; i < 4; i++)
        #pragma unroll
        for (int j = 0; j < 4; j++)
            #pragma unroll
            for (int e = 0; e < 4; e++) acc[i][j][e] = 0.f;

    load_stage(0);

    // ldmatrix lane addressing (byte units within a [128][40] tile)
    const uint32_t a_row  = (uint32_t)(warp_m * 64 + (lid & 15));
    const uint32_t a_koff = (uint32_t)((lid >> 4) * 16);
    const uint32_t b_row  = (uint32_t)(warp_n * 32 + ((lid >> 4) * 8) + (lid & 7));
    const uint32_t b_koff = (uint32_t)(((lid >> 3) & 1) * 16);

    for (int c = 0; c < NC; c++) {
        cp_wait0();
        __syncthreads();
        if (c + 1 < NC) load_stage(c + 1);   // overlaps with MMA below

        const uint32_t sbase = sb + (uint32_t)(c & 1) * STAGE_BYTES;
        const uint32_t tAh = sbase + 0 * TILE_BYTES;
        const uint32_t tAl = sbase + 1 * TILE_BYTES;
        const uint32_t tBh = sbase + 2 * TILE_BYTES;
        const uint32_t tBl = sbase + 3 * TILE_BYTES;

        #pragma unroll
        for (int ks = 0; ks < 2; ks++) {
            const uint32_t kb = (uint32_t)(ks * 32);
            uint32_t fbh[2][4], fbl[2][4];
            #pragma unroll
            for (int nb = 0; nb < 2; nb++) {
                uint32_t bo = ((b_row + nb * 16) * LDS_E) * 2 + b_koff + kb;
                ldsm4(fbh[nb], tBh + bo);
                ldsm4(fbl[nb], tBl + bo);
            }
            #pragma unroll
            for (int ma = 0; ma < 4; ma++) {
                uint32_t fah[4], fal[4];
                uint32_t ao = ((a_row + ma * 16) * LDS_E) * 2 + a_koff + kb;
                ldsm4(fah, tAh + ao);
                ldsm4(fal, tAl + ao);
                #pragma unroll
                for (int na = 0; na < 4; na++) {
                    const uint32_t* bh = &fbh[na >> 1][(na & 1) * 2];
                    const uint32_t* bl = &fbl[na >> 1][(na & 1) * 2];
                    mma16816(acc[ma][na], fah, bh);
                    mma16816(acc[ma][na], fah, bl);
                    mma16816(acc[ma][na], fal, bh);
                }
            }
        }
    }

    // ---- epilogue ----
    const int mrow = m0 + warp_m * 64 + (lid >> 2);
    const int ncol = n0 + warp_n * 32 + (lid & 3) * 2;
    #pragma unroll
    for (int ma = 0; ma < 4; ma++) {
        #pragma unroll
        for (int na = 0; na < 4; na++) {
            int cc = ncol + na * 8;
            float b0 = 0.f, b1 = 0.f;
            if (BIAS) { b0 = bias[cc]; b1 = bias[cc + 1]; }
            float2 v0 = make_float2(acc[ma][na][0] + b0, acc[ma][na][1] + b1);
            float2 v1 = make_float2(acc[ma][na][2] + b0, acc[ma][na][3] + b1);
            *(float2*)(C + (size_t)(mrow + ma * 16)     * N + cc) = v0;
            *(float2*)(C + (size_t)(mrow + ma * 16 + 8) * N + cc) = v1;
        }
    }
}

// ============================================================
// qp[b,n,h] = tanh(x @ Wqf + bqf) @ Wqp  (dyn bias factorization)
// 256 thr / 32 rows per block; x in padded smem (stride 513 ->
// conflict-free across rows); Wqf^T gives warp-uniform float4 LDGs.
// ============================================================
__global__ __launch_bounds__(256)
void qp_kernel(const float* __restrict__ x,
               const float* __restrict__ bqf, const float* __restrict__ Wqp)
{
    __shared__ float xs[32 * 513];
    __shared__ float qf[32 * 64];
    const int m0 = blockIdx.x * 32;
    const int tid = threadIdx.x;

    // load 32x512 floats, vectorized
    for (int u = tid; u < 32 * 128; u += 256) {
        int r = u >> 7, q = u & 127;
        float4 v = *(const float4*)(x + (size_t)(m0 + r) * Dd + q * 4);
        float* d = xs + r * 513 + q * 4;
        d[0] = v.x; d[1] = v.y; d[2] = v.z; d[3] = v.w;
    }
    __syncthreads();

    // thread: row r = lane (conflict-free), col group cg -> 8 cols
    const int r  = tid & 31;
    const int cg = tid >> 5;           // 0..7
    float acc[8];
    #pragma unroll
    for (int j = 0; j < 8; j++) acc[j] = bqf[cg * 8 + j];

    const float* xr = xs + r * 513;
    for (int i = 0; i < 512; i += 4) {
        float x0 = xr[i], x1 = xr[i + 1], x2 = xr[i + 2], x3 = xr[i + 3];
        #pragma unroll
        for (int j = 0; j < 8; j++) {
            float4 w = *(const float4*)(g_wqft + (size_t)(cg * 8 + j) * Dd + i);
            acc[j] += x0 * w.x + x1 * w.y + x2 * w.z + x3 * w.w;
        }
    }
    #pragma unroll
    for (int j = 0; j < 8; j++) qf[r * 64 + cg * 8 + j] = tanhf(acc[j]);
    __syncthreads();

    // qp = qf @ Wqp : 32 rows x 8 heads = 256 outputs, one per thread
    const int r2 = tid >> 3, h = tid & 7;
    float a = 0.f;
    #pragma unroll
    for (int c = 0; c < 64; c++) a += qf[r2 * 64 + c] * Wqp[c * 8 + h];
    g_qp[(size_t)(m0 + r2) * 8 + h] = a;
}

// ============================================================
// Fused LayerNorm+residual + attention, one block per batch b.
// ============================================================
#define LNROW 513
#define SM_BUF   (3 * Nn * LNROW)
#define SM_SC    (SM_BUF)
#define SM_REL   (SM_SC + Hh * Nn * Nn)
#define SM_QPH   (SM_REL + Hh * (2 * Nn - 1))
#define FUSED_SMEM_F (SM_QPH + Nn * Hh)
#define FUSED_SMEM (FUSED_SMEM_F * 4)

__global__ __launch_bounds__(512, 1)
void ln_attn_kernel(const float* __restrict__ xin,
                    const float* __restrict__ gq_g, const float* __restrict__ gq_b,
                    const float* __restrict__ gk_g, const float* __restrict__ gk_b,
                    const float* __restrict__ gv_g, const float* __restrict__ gv_b,
                    const float* __restrict__ rel_table,
                    const float* __restrict__ gsb,
                    const float* __restrict__ alpha_p,
                    const float* __restrict__ bqp)
{
    extern __shared__ float sm[];
    float* buf  = sm;                 // [3][20][513]
    float* sc   = sm + SM_SC;         // [8][20][20]
    float* relh = sm + SM_REL;        // [8][39]
    float* qph  = sm + SM_QPH;        // [20][8]

    const int b = blockIdx.x;
    const int tid = threadIdx.x;
    const int wid = tid >> 5, lid = tid & 31;

    for (int i = tid; i < 3 * Nn * Dd; i += 512) {
        int p = i / (Nn * Dd);
        int rem = i - p * Nn * Dd;
        int n = rem >> 9, d = rem & 511;
        buf[(p * Nn + n) * LNROW + d] =
            g_conv[(size_t)(b * Nn + n) * K3 + p * Dd + d];
    }
    if (tid < Hh * (2 * Nn - 1)) relh[tid] = rel_table[(tid % (2 * Nn - 1)) * Hh + (tid / (2 * Nn - 1))];
    else if (tid >= 480 && tid < 480 + Nn) {
        int n = tid - 480;
        #pragma unroll
        for (int h = 0; h < Hh; h++)
            qph[n * Hh + h] = g_qp[(size_t)(b * Nn + n) * Hh + h];
    }
    __syncthreads();

    for (int r = wid; r < 3 * Nn; r += 16) {
        int p = r / Nn, n = r - p * Nn;
        float* row = buf + r * LNROW;
        float s = 0.f, sq = 0.f;
        #pragma unroll
        for (int j = 0; j < 16; j++) {
            float v = row[lid + j * 32];
            s += v; sq += v * v;
        }
        #pragma unroll
        for (int o = 16; o > 0; o >>= 1) {
            s  += __shfl_xor_sync(0xffffffffu, s,  o);
            sq += __shfl_xor_sync(0xffffffffu, sq, o);
        }
        float mean = s * (1.f / 512.f);
        float var  = sq * (1.f / 512.f) - mean * mean;
        float rstd = rsqrtf(var + 1e-5f);
        const float* g  = (p == 0) ? gq_g : (p == 1) ? gk_g : gv_g;
        const float* be = (p == 0) ? gq_b : (p == 1) ? gk_b : gv_b;
        const float* xr = xin + (size_t)(b * Nn + n) * Dd;
        #pragma unroll
        for (int j = 0; j < 16; j++) {
            int d = lid + j * 32;
            row[d] = xr[d] + (row[d] - mean) * rstd * g[d] + be[d];
        }
    }
    __syncthreads();

    const float alpha = *alpha_p;
    const float* q = buf;
    const float* k = buf + Nn * LNROW;
    const float* v = buf + 2 * Nn * LNROW;
    for (int t = tid; t < Hh * Nn * Nn; t += 512) {
        int h = t / (Nn * Nn);
        int rem = t - h * Nn * Nn;
        int n = rem / Nn, m = rem - n * Nn;
        const float* qr = q + n * LNROW + h * 64;
        const float* kr = k + m * LNROW + h * 64;
        float a = 0.f;
        #pragma unroll
        for (int d = 0; d < 64; d++) a += qr[d] * kr[d];
        a = a * 0.125f
          + relh[h * (2 * Nn - 1) + n - m + Nn - 1]
          + alpha * gsb[(size_t)(h * Nn + n) * Nn + m]
          + (qph[n * Hh + h] - qph[m * Hh + h]) + bqp[h];
        sc[t] = a;
    }
    __syncthreads();

    if (tid < Hh * Nn) {
        float* row = sc + tid * Nn;
        float mx = -1e30f;
        #pragma unroll
        for (int m = 0; m < Nn; m++) mx = fmaxf(mx, row[m]);
        float s = 0.f;
        #pragma unroll
        for (int m = 0; m < Nn; m++) { float e = expf(row[m] - mx); row[m] = e; s += e; }
        float inv = 1.f / s;
        #pragma unroll
        for (int m = 0; m < Nn; m++) row[m] *= inv;
    }
    __syncthreads();

    for (int t = tid; t < Hh * Nn * 64; t += 512) {
        int hn = t >> 6, d = t & 63;
        int h = hn / Nn, n = hn - h * Nn;
        const float* ar = sc + (h * Nn + n) * Nn;
        const float* vb = v + h * 64 + d;
        float a = 0.f;
        #pragma unroll
        for (int m = 0; m < Nn; m++) a += ar[m] * vb[m * LNROW];
        size_t dst = (size_t)(b * Nn + n) * Dd + h * 64 + d;
        __nv_bfloat16 hi = __float2bfloat16(a);
        g_ah[dst] = hi;
        g_al[dst] = __float2bfloat16(a - __bfloat162float(hi));
    }
}

// ============================================================
// launch
// ============================================================
extern "C" void kernel_launch(void* const* d_in, const int* in_sizes, int n_in,
                              void* d_out, int out_size)
{
    const float* x         = (const float*)d_in[0];
    const float* Wq        = (const float*)d_in[1];
    const float* Wk        = (const float*)d_in[2];
    const float* Wv        = (const float*)d_in[3];
    const float* gq_g      = (const float*)d_in[4];
    const float* gq_b      = (const float*)d_in[5];
    const float* gk_g      = (const float*)d_in[6];
    const float* gk_b      = (const float*)d_in[7];
    const float* gv_g      = (const float*)d_in[8];
    const float* gv_b      = (const float*)d_in[9];
    const float* rel_table = (const float*)d_in[10];
    const float* gsb       = (const float*)d_in[11];
    const float* alpha     = (const float*)d_in[12];
    const float* Wqf       = (const float*)d_in[13];
    const float* bqf       = (const float*)d_in[14];
    const float* Wqp       = (const float*)d_in[15];
    const float* bqp       = (const float*)d_in[16];
    const float* Wo        = (const float*)d_in[17];
    const float* bo        = (const float*)d_in[18];

    cudaFuncSetAttribute(tc_gemm<1, false>, cudaFuncAttributeMaxDynamicSharedMemorySize, GEMM_SMEM);
    cudaFuncSetAttribute(tc_gemm<0, true>,  cudaFuncAttributeMaxDynamicSharedMemorySize, GEMM_SMEM);
    cudaFuncSetAttribute(ln_attn_kernel,    cudaFuncAttributeMaxDynamicSharedMemorySize, FUSED_SMEM);

    __nv_bfloat16 *pxh, *pxl, *pwth, *pwtl, *pah, *pal, *pwoh, *pwol;
    float *pConv;
    cudaGetSymbolAddress((void**)&pxh, g_xh);
    cudaGetSymbolAddress((void**)&pxl, g_xl);
    cudaGetSymbolAddress((void**)&pwth, g_wth);
    cudaGetSymbolAddress((void**)&pwtl, g_wtl);
    cudaGetSymbolAddress((void**)&pah, g_ah);
    cudaGetSymbolAddress((void**)&pal, g_al);
    cudaGetSymbolAddress((void**)&pwoh, g_woh);
    cudaGetSymbolAddress((void**)&pwol, g_wol);
    cudaGetSymbolAddress((void**)&pConv, g_conv);

    // 1. precompute bf16 hi/lo splits + transposed Wqf
    split_x<<<(Mrows * Dd + 255) / 256, 256>>>(x);
    repack_w<<<(K3 * K3 + 255) / 256, 256>>>(Wq, Wk, Wv);
    repack_wo<<<(Dd * Dd + 255) / 256, 256>>>(Wo, Wqf);

    // 2. fused QKV conv as im2col GEMM
    {
        dim3 grid(K3 / 128, Mrows / 128);   // (12, 320)
        tc_gemm<1, false><<<grid, 256, GEMM_SMEM>>>(pxh, pxl, pwth, pwtl,
                                                    pConv, nullptr, K3, K3);
    }

    // 3. dynamic-bias projection qp
    qp_kernel<<<Mrows / 32, 256>>>(x, bqf, Wqp);

    // 4. fused LN+residual + attention (per batch), emits bf16 hi/lo
    ln_attn_kernel<<<Bsz, 512, FUSED_SMEM>>>(x, gq_g, gq_b, gk_g, gk_b, gv_g, gv_b,
                                             rel_table, gsb, alpha, bqp);

    // 5. output projection: [40960 x 512] @ Wo + bo
    {
        dim3 grid(Dd / 128, Mrows / 128);   // (4, 320)
        tc_gemm<0, true><<<grid, 256, GEMM_SMEM>>>(pah, pal, pwoh, pwol,
                                                   (float*)d_out, bo, Dd, Dd);
    }
}

// round 11
// speedup vs baseline: 1.0493x; 1.0493x over previous
#include <cuda_runtime.h>
#include <cuda_bf16.h>
#include <math.h>
#include <stdint.h>
#include <stddef.h>

// ------------ problem constants ------------
#define Bsz   2048
#define Nn    20
#define Dd    512
#define Hh    8
#define Mrows (Bsz*Nn)     // 40960
#define K3    (3*Dd)       // 1536

// ------------ scratch (static __device__) ------------
__device__ __align__(256) float g_conv[(size_t)Mrows * K3];        // conv GEMM out (fp32)
__device__ __align__(256) float g_qp[(size_t)Mrows * Hh];
__device__ __align__(256) float g_wqft[(size_t)64 * Dd];           // Wqf^T [c][i]
__device__ __align__(256) __nv_bfloat16 g_xh[(size_t)Mrows * Dd];  // x split hi/lo
__device__ __align__(256) __nv_bfloat16 g_xl[(size_t)Mrows * Dd];
__device__ __align__(256) __nv_bfloat16 g_ah[(size_t)Mrows * Dd];  // attn out split
__device__ __align__(256) __nv_bfloat16 g_al[(size_t)Mrows * Dd];
__device__ __align__(256) __nv_bfloat16 g_wth[(size_t)K3 * K3];    // W^T concat [oc][kk]
__device__ __align__(256) __nv_bfloat16 g_wtl[(size_t)K3 * K3];
__device__ __align__(256) __nv_bfloat16 g_woh[(size_t)Dd * Dd];    // Wo^T [n][k]
__device__ __align__(256) __nv_bfloat16 g_wol[(size_t)Dd * Dd];

// ------------ small PTX helpers (plain-sm_103-safe) ------------
__device__ __forceinline__ uint32_t smem_u32(const void* p) {
    uint32_t a;
    asm("{ .reg .u64 t; cvta.to.shared.u64 t, %1; cvt.u32.u64 %0, t; }" : "=r"(a) : "l"(p));
    return a;
}
__device__ __forceinline__ void cp_async16(uint32_t saddr, const void* gaddr, uint32_t srcsize) {
    asm volatile("cp.async.cg.shared.global [%0], [%1], 16, %2;"
                 :: "r"(saddr), "l"(gaddr), "r"(srcsize) : "memory");
}
__device__ __forceinline__ void cp_commit() { asm volatile("cp.async.commit_group;" ::: "memory"); }
__device__ __forceinline__ void cp_wait0()  { asm volatile("cp.async.wait_group 0;" ::: "memory"); }
__device__ __forceinline__ void cp_wait1()  { asm volatile("cp.async.wait_group 1;" ::: "memory"); }

__device__ __forceinline__ void ldsm4(uint32_t* r, uint32_t addr) {
    asm volatile("ldmatrix.sync.aligned.m8n8.x4.shared.b16 {%0,%1,%2,%3}, [%4];"
                 : "=r"(r[0]), "=r"(r[1]), "=r"(r[2]), "=r"(r[3]) : "r"(addr));
}
__device__ __forceinline__ void mma16816(float* c, const uint32_t* a, const uint32_t* b) {
    asm volatile("mma.sync.aligned.m16n8k16.row.col.f32.bf16.bf16.f32 "
                 "{%0,%1,%2,%3}, {%4,%5,%6,%7}, {%8,%9}, {%0,%1,%2,%3};"
                 : "+f"(c[0]), "+f"(c[1]), "+f"(c[2]), "+f"(c[3])
                 : "r"(a[0]), "r"(a[1]), "r"(a[2]), "r"(a[3]), "r"(b[0]), "r"(b[1]));
}

// ============================================================
// precompute kernels
// ============================================================
__global__ void split_x(const float* __restrict__ x) {
    size_t i = (size_t)blockIdx.x * 256 + threadIdx.x;
    if (i >= (size_t)Mrows * Dd) return;
    float v = x[i];
    __nv_bfloat16 h = __float2bfloat16(v);
    g_xh[i] = h;
    g_xl[i] = __float2bfloat16(v - __bfloat162float(h));
}

__global__ void repack_w(const float* __restrict__ Wq,
                         const float* __restrict__ Wk,
                         const float* __restrict__ Wv) {
    size_t idx = (size_t)blockIdx.x * 256 + threadIdx.x;
    if (idx >= (size_t)K3 * K3) return;
    int oc = (int)(idx / K3);
    int kk = (int)(idx - (size_t)oc * K3);
    int t = kk >> 9, i = kk & 511;
    int p = oc >> 9, o = oc & 511;
    const float* W = (p == 0) ? Wq : (p == 1) ? Wk : Wv;
    float v = W[(size_t)o * K3 + i * 3 + t];
    __nv_bfloat16 h = __float2bfloat16(v);
    g_wth[idx] = h;
    g_wtl[idx] = __float2bfloat16(v - __bfloat162float(h));
}

__global__ void repack_wo(const float* __restrict__ Wo, const float* __restrict__ Wqf) {
    int idx = blockIdx.x * 256 + threadIdx.x;
    if (idx < 64 * Dd) {
        int c = idx >> 9, i = idx & 511;
        g_wqft[idx] = Wqf[(size_t)i * 64 + c];
    }
    if (idx >= Dd * Dd) return;
    int n = idx >> 9, k = idx & 511;
    float v = Wo[(size_t)k * Dd + n];
    __nv_bfloat16 h = __float2bfloat16(v);
    g_woh[idx] = h;
    g_wol[idx] = __float2bfloat16(v - __bfloat162float(h));
}

// ============================================================
// warp-mma bf16 GEMM (R8-proven loop): C = A * B^T; bf16x3 split.
// CTA 128x128, 256 thr (8 warps 2x4), warp tile 64x32, BK=32,
// double buffer, prefetch BEFORE wait (overlaps GMEM latency):
//   load(c+1) -> cp_wait1 -> barrier -> MMA(c) -> barrier
// 2 CTAs/SM via __launch_bounds__(256,2).
// ============================================================
#define LDS_E 40
#define TILE_E (128 * LDS_E)
#define TILE_BYTES (TILE_E * 2)          // 10240 B
#define STAGE_BYTES (4 * TILE_BYTES)     // 40960 B
#define GEMM_SMEM (2 * STAGE_BYTES)      // 81920 B

template<int MODE, bool BIAS>
__global__ __launch_bounds__(256, 2)
void tc_gemm(const __nv_bfloat16* __restrict__ Ah, const __nv_bfloat16* __restrict__ Al,
             const __nv_bfloat16* __restrict__ Bh, const __nv_bfloat16* __restrict__ Bl,
             float* __restrict__ C, const float* __restrict__ bias, int K, int N)
{
    extern __shared__ __nv_bfloat16 smem[];
    const uint32_t sb = smem_u32(smem);
    const int tid = threadIdx.x;
    const int wid = tid >> 5, lid = tid & 31;
    const int warp_m = wid >> 2;      // 0..1  (64 rows)
    const int warp_n = wid & 3;       // 0..3  (32 cols)
    const int m0 = blockIdx.y * 128, n0 = blockIdx.x * 128;
    const int NC = K >> 5;

    auto load_stage = [&](int c) {
        const int buf = c & 1;
        const int kk0 = c << 5;
        uint32_t sbase = sb + (uint32_t)buf * STAGE_BYTES;
        #pragma unroll
        for (int it = 0; it < 2; it++) {
            int id = tid + it * 256;            // 0..511
            int r = id >> 2, q = id & 3;        // row, 16B quad
            uint32_t soff = (uint32_t)(r * LDS_E + q * 8) * 2;
            size_t aoff; uint32_t vsz = 16;
            if (MODE == 1) {
                int gm = m0 + r;
                int bb = gm / Nn, nn = gm - bb * Nn;
                int t = kk0 >> 9;
                int d = (kk0 & 511) + q * 8;
                int jj = nn + t - 1;
                if (jj < 0 || jj >= Nn) { vsz = 0; jj = 0; }
                aoff = ((size_t)(bb * Nn + jj) << 9) + d;
            } else {
                aoff = (size_t)(m0 + r) * K + kk0 + q * 8;
            }
            cp_async16(sbase + 0 * TILE_BYTES + soff, Ah + aoff, vsz);
            cp_async16(sbase + 1 * TILE_BYTES + soff, Al + aoff, vsz);
            size_t boff = (size_t)(n0 + r) * K + kk0 + q * 8;
            cp_async16(sbase + 2 * TILE_BYTES + soff, Bh + boff, 16);
            cp_async16(sbase + 3 * TILE_BYTES + soff, Bl + boff, 16);
        }
        cp_commit();
    };

    float acc[4][4][4];
    #pragma unroll
    for (int i = 0; i < 4; i++)
        #pragma unroll
        for (int j = 0; j < 4; j++)
            #pragma unroll
            for (int e = 0; e < 4; e++) acc[i][j][e] = 0.f;

    load_stage(0);

    const uint32_t a_row  = (uint32_t)(warp_m * 64 + (lid & 15));
    const uint32_t a_koff = (uint32_t)((lid >> 4) * 16);
    const uint32_t b_row  = (uint32_t)(warp_n * 32 + ((lid >> 4) * 8) + (lid & 7));
    const uint32_t b_koff = (uint32_t)(((lid >> 3) & 1) * 16);

    for (int c = 0; c < NC; c++) {
        if (c + 1 < NC) { load_stage(c + 1); cp_wait1(); }
        else            { cp_wait0(); }
        __syncthreads();

        const uint32_t sbase = sb + (uint32_t)(c & 1) * STAGE_BYTES;
        const uint32_t tAh = sbase + 0 * TILE_BYTES;
        const uint32_t tAl = sbase + 1 * TILE_BYTES;
        const uint32_t tBh = sbase + 2 * TILE_BYTES;
        const uint32_t tBl = sbase + 3 * TILE_BYTES;

        #pragma unroll
        for (int ks = 0; ks < 2; ks++) {
            const uint32_t kb = (uint32_t)(ks * 32);
            uint32_t fbh[2][4], fbl[2][4];
            #pragma unroll
            for (int nb = 0; nb < 2; nb++) {
                uint32_t bo = ((b_row + nb * 16) * LDS_E) * 2 + b_koff + kb;
                ldsm4(fbh[nb], tBh + bo);
                ldsm4(fbl[nb], tBl + bo);
            }
            #pragma unroll
            for (int ma = 0; ma < 4; ma++) {
                uint32_t fah[4], fal[4];
                uint32_t ao = ((a_row + ma * 16) * LDS_E) * 2 + a_koff + kb;
                ldsm4(fah, tAh + ao);
                ldsm4(fal, tAl + ao);
                #pragma unroll
                for (int na = 0; na < 4; na++) {
                    const uint32_t* bh = &fbh[na >> 1][(na & 1) * 2];
                    const uint32_t* bl = &fbl[na >> 1][(na & 1) * 2];
                    mma16816(acc[ma][na], fah, bh);
                    mma16816(acc[ma][na], fah, bl);
                    mma16816(acc[ma][na], fal, bh);
                }
            }
        }
        __syncthreads();
    }

    const int mrow = m0 + warp_m * 64 + (lid >> 2);
    const int ncol = n0 + warp_n * 32 + (lid & 3) * 2;
    #pragma unroll
    for (int ma = 0; ma < 4; ma++) {
        #pragma unroll
        for (int na = 0; na < 4; na++) {
            int cc = ncol + na * 8;
            float b0 = 0.f, b1 = 0.f;
            if (BIAS) { b0 = bias[cc]; b1 = bias[cc + 1]; }
            float2 v0 = make_float2(acc[ma][na][0] + b0, acc[ma][na][1] + b1);
            float2 v1 = make_float2(acc[ma][na][2] + b0, acc[ma][na][3] + b1);
            *(float2*)(C + (size_t)(mrow + ma * 16)     * N + cc) = v0;
            *(float2*)(C + (size_t)(mrow + ma * 16 + 8) * N + cc) = v1;
        }
    }
}

// ============================================================
// qp[b,n,h] = tanh(x @ Wqf + bqf) @ Wqp  (dyn bias factorization)
// ============================================================
__global__ __launch_bounds__(256)
void qp_kernel(const float* __restrict__ x,
               const float* __restrict__ bqf, const float* __restrict__ Wqp)
{
    __shared__ float xs[32 * 513];
    __shared__ float qf[32 * 64];
    const int m0 = blockIdx.x * 32;
    const int tid = threadIdx.x;

    for (int u = tid; u < 32 * 128; u += 256) {
        int r = u >> 7, q = u & 127;
        float4 v = *(const float4*)(x + (size_t)(m0 + r) * Dd + q * 4);
        float* d = xs + r * 513 + q * 4;
        d[0] = v.x; d[1] = v.y; d[2] = v.z; d[3] = v.w;
    }
    __syncthreads();

    const int r  = tid & 31;
    const int cg = tid >> 5;
    float acc[8];
    #pragma unroll
    for (int j = 0; j < 8; j++) acc[j] = bqf[cg * 8 + j];

    const float* xr = xs + r * 513;
    for (int i = 0; i < 512; i += 4) {
        float x0 = xr[i], x1 = xr[i + 1], x2 = xr[i + 2], x3 = xr[i + 3];
        #pragma unroll
        for (int j = 0; j < 8; j++) {
            float4 w = *(const float4*)(g_wqft + (size_t)(cg * 8 + j) * Dd + i);
            acc[j] += x0 * w.x + x1 * w.y + x2 * w.z + x3 * w.w;
        }
    }
    #pragma unroll
    for (int j = 0; j < 8; j++) qf[r * 64 + cg * 8 + j] = tanhf(acc[j]);
    __syncthreads();

    const int r2 = tid >> 3, h = tid & 7;
    float a = 0.f;
    #pragma unroll
    for (int c = 0; c < 64; c++) a += qf[r2 * 64 + c] * Wqp[c * 8 + h];
    g_qp[(size_t)(m0 + r2) * 8 + h] = a;
}

// ============================================================
// Fused LN+residual + attention, one block per batch b.
// Only q,k slabs resident (2x20x513); v stats computed streaming,
// v materialized into the dead q-slab after softmax.
// ~97KB smem -> 2 CTAs/SM.
// ============================================================
#define LNROW 513
#define SM2_SC   (2 * Nn * LNROW)              // 20520
#define SM2_REL  (SM2_SC + Hh * Nn * Nn)       // +3200
#define SM2_QPH  (SM2_REL + Hh * (2 * Nn - 1)) // +312
#define SM2_VM   (SM2_QPH + Nn * Hh)           // +160
#define SM2_VR   (SM2_VM + Nn)                 // +20
#define FUSED2_F (SM2_VR + Nn)                 // +20 => 24232 floats
#define FUSED2_B (FUSED2_F * 4)                // 96928 bytes

__global__ __launch_bounds__(512, 2)
void ln_attn_kernel(const float* __restrict__ xin,
                    const float* __restrict__ gq_g, const float* __restrict__ gq_b,
                    const float* __restrict__ gk_g, const float* __restrict__ gk_b,
                    const float* __restrict__ gv_g, const float* __restrict__ gv_b,
                    const float* __restrict__ rel_table,
                    const float* __restrict__ gsb,
                    const float* __restrict__ alpha_p,
                    const float* __restrict__ bqp)
{
    extern __shared__ float sm[];
    float* buf   = sm;                 // [2][20][513]  q,k  (later: slab0 = v)
    float* sc    = sm + SM2_SC;        // [8][20][20]
    float* relh  = sm + SM2_REL;       // [8][39]
    float* qph   = sm + SM2_QPH;       // [20][8]
    float* vmean = sm + SM2_VM;        // [20]
    float* vrstd = sm + SM2_VR;        // [20]

    const int b = blockIdx.x;
    const int tid = threadIdx.x;
    const int wid = tid >> 5, lid = tid & 31;

    // ---- 1. load q,k conv slabs; bias tables ----
    for (int i = tid; i < 2 * Nn * Dd; i += 512) {
        int p = i / (Nn * Dd);
        int rem = i - p * Nn * Dd;
        int n = rem >> 9, d = rem & 511;
        buf[(p * Nn + n) * LNROW + d] =
            g_conv[(size_t)(b * Nn + n) * K3 + p * Dd + d];
    }
    if (tid < Hh * (2 * Nn - 1)) relh[tid] = rel_table[(tid % (2 * Nn - 1)) * Hh + (tid / (2 * Nn - 1))];
    else if (tid >= 480 && tid < 480 + Nn) {
        int n = tid - 480;
        #pragma unroll
        for (int h = 0; h < Hh; h++)
            qph[n * Hh + h] = g_qp[(size_t)(b * Nn + n) * Hh + h];
    }

    // ---- 1b. v statistics (streaming, nothing stored but mean/rstd) ----
    for (int r = wid; r < Nn; r += 16) {
        const float* vr = g_conv + (size_t)(b * Nn + r) * K3 + 2 * Dd;
        float s = 0.f, sq = 0.f;
        #pragma unroll
        for (int j = 0; j < 16; j++) {
            float v = vr[lid + j * 32];
            s += v; sq += v * v;
        }
        #pragma unroll
        for (int o = 16; o > 0; o >>= 1) {
            s  += __shfl_xor_sync(0xffffffffu, s,  o);
            sq += __shfl_xor_sync(0xffffffffu, sq, o);
        }
        if (lid == 0) {
            float mean = s * (1.f / 512.f);
            float var  = sq * (1.f / 512.f) - mean * mean;
            vmean[r] = mean;
            vrstd[r] = rsqrtf(var + 1e-5f);
        }
    }
    __syncthreads();

    // ---- 2. LN + residual on q,k slabs (40 rows) ----
    for (int r = wid; r < 2 * Nn; r += 16) {
        int p = r / Nn, n = r - p * Nn;
        float* row = buf + r * LNROW;
        float s = 0.f, sq = 0.f;
        #pragma unroll
        for (int j = 0; j < 16; j++) {
            float v = row[lid + j * 32];
            s += v; sq += v * v;
        }
        #pragma unroll
        for (int o = 16; o > 0; o >>= 1) {
            s  += __shfl_xor_sync(0xffffffffu, s,  o);
            sq += __shfl_xor_sync(0xffffffffu, sq, o);
        }
        float mean = s * (1.f / 512.f);
        float var  = sq * (1.f / 512.f) - mean * mean;
        float rstd = rsqrtf(var + 1e-5f);
        const float* g  = (p == 0) ? gq_g : gk_g;
        const float* be = (p == 0) ? gq_b : gk_b;
        const float* xr = xin + (size_t)(b * Nn + n) * Dd;
        #pragma unroll
        for (int j = 0; j < 16; j++) {
            int d = lid + j * 32;
            row[d] = xr[d] + (row[d] - mean) * rstd * g[d] + be[d];
        }
    }
    __syncthreads();

    // ---- 3. scores ----
    const float alpha = *alpha_p;
    const float* q = buf;
    const float* k = buf + Nn * LNROW;
    for (int t = tid; t < Hh * Nn * Nn; t += 512) {
        int h = t / (Nn * Nn);
        int rem = t - h * Nn * Nn;
        int n = rem / Nn, m = rem - n * Nn;
        const float* qr = q + n * LNROW + h * 64;
        const float* kr = k + m * LNROW + h * 64;
        float a = 0.f;
        #pragma unroll
        for (int d = 0; d < 64; d++) a += qr[d] * kr[d];
        a = a * 0.125f
          + relh[h * (2 * Nn - 1) + n - m + Nn - 1]
          + alpha * gsb[(size_t)(h * Nn + n) * Nn + m]
          + (qph[n * Hh + h] - qph[m * Hh + h]) + bqp[h];
        sc[t] = a;
    }
    __syncthreads();

    // ---- 4. softmax ----
    if (tid < Hh * Nn) {
        float* row = sc + tid * Nn;
        float mx = -1e30f;
        #pragma unroll
        for (int m = 0; m < Nn; m++) mx = fmaxf(mx, row[m]);
        float s = 0.f;
        #pragma unroll
        for (int m = 0; m < Nn; m++) { float e = expf(row[m] - mx); row[m] = e; s += e; }
        float inv = 1.f / s;
        #pragma unroll
        for (int m = 0; m < Nn; m++) row[m] *= inv;
    }
    __syncthreads();

    // ---- 5. materialize v = LN(conv_v)+x into the dead q-slab ----
    for (int i = tid; i < Nn * Dd; i += 512) {
        int n = i >> 9, d = i & 511;
        float cv = g_conv[(size_t)(b * Nn + n) * K3 + 2 * Dd + d];
        float val = xin[(size_t)(b * Nn + n) * Dd + d]
                  + (cv - vmean[n]) * vrstd[n] * gv_g[d] + gv_b[d];
        buf[n * LNROW + d] = val;
    }
    __syncthreads();

    // ---- 6. out = attn @ v, write bf16 hi/lo ----
    const float* v = buf;
    for (int t = tid; t < Hh * Nn * 64; t += 512) {
        int hn = t >> 6, d = t & 63;
        int h = hn / Nn, n = hn - h * Nn;
        const float* ar = sc + (h * Nn + n) * Nn;
        const float* vb = v + h * 64 + d;
        float a = 0.f;
        #pragma unroll
        for (int m = 0; m < Nn; m++) a += ar[m] * vb[m * LNROW];
        size_t dst = (size_t)(b * Nn + n) * Dd + h * 64 + d;
        __nv_bfloat16 hi = __float2bfloat16(a);
        g_ah[dst] = hi;
        g_al[dst] = __float2bfloat16(a - __bfloat162float(hi));
    }
}

// ============================================================
// launch
// ============================================================
extern "C" void kernel_launch(void* const* d_in, const int* in_sizes, int n_in,
                              void* d_out, int out_size)
{
    const float* x         = (const float*)d_in[0];
    const float* Wq        = (const float*)d_in[1];
    const float* Wk        = (const float*)d_in[2];
    const float* Wv        = (const float*)d_in[3];
    const float* gq_g      = (const float*)d_in[4];
    const float* gq_b      = (const float*)d_in[5];
    const float* gk_g      = (const float*)d_in[6];
    const float* gk_b      = (const float*)d_in[7];
    const float* gv_g      = (const float*)d_in[8];
    const float* gv_b      = (const float*)d_in[9];
    const float* rel_table = (const float*)d_in[10];
    const float* gsb       = (const float*)d_in[11];
    const float* alpha     = (const float*)d_in[12];
    const float* Wqf       = (const float*)d_in[13];
    const float* bqf       = (const float*)d_in[14];
    const float* Wqp       = (const float*)d_in[15];
    const float* bqp       = (const float*)d_in[16];
    const float* Wo        = (const float*)d_in[17];
    const float* bo        = (const float*)d_in[18];

    cudaFuncSetAttribute(tc_gemm<1, false>, cudaFuncAttributeMaxDynamicSharedMemorySize, GEMM_SMEM);
    cudaFuncSetAttribute(tc_gemm<0, true>,  cudaFuncAttributeMaxDynamicSharedMemorySize, GEMM_SMEM);
    cudaFuncSetAttribute(ln_attn_kernel,    cudaFuncAttributeMaxDynamicSharedMemorySize, FUSED2_B);

    __nv_bfloat16 *pxh, *pxl, *pwth, *pwtl, *pah, *pal, *pwoh, *pwol;
    float *pConv;
    cudaGetSymbolAddress((void**)&pxh, g_xh);
    cudaGetSymbolAddress((void**)&pxl, g_xl);
    cudaGetSymbolAddress((void**)&pwth, g_wth);
    cudaGetSymbolAddress((void**)&pwtl, g_wtl);
    cudaGetSymbolAddress((void**)&pah, g_ah);
    cudaGetSymbolAddress((void**)&pal, g_al);
    cudaGetSymbolAddress((void**)&pwoh, g_woh);
    cudaGetSymbolAddress((void**)&pwol, g_wol);
    cudaGetSymbolAddress((void**)&pConv, g_conv);

    // 1. precompute bf16 hi/lo splits + transposed Wqf
    split_x<<<(Mrows * Dd + 255) / 256, 256>>>(x);
    repack_w<<<(K3 * K3 + 255) / 256, 256>>>(Wq, Wk, Wv);
    repack_wo<<<(Dd * Dd + 255) / 256, 256>>>(Wo, Wqf);

    // 2. fused QKV conv as im2col GEMM
    {
        dim3 grid(K3 / 128, Mrows / 128);   // (12, 320)
        tc_gemm<1, false><<<grid, 256, GEMM_SMEM>>>(pxh, pxl, pwth, pwtl,
                                                    pConv, nullptr, K3, K3);
    }

    // 3. dynamic-bias projection qp
    qp_kernel<<<Mrows / 32, 256>>>(x, bqf, Wqp);

    // 4. fused LN+residual + attention (per batch), emits bf16 hi/lo
    ln_attn_kernel<<<Bsz, 512, FUSED2_B>>>(x, gq_g, gq_b, gk_g, gk_b, gv_g, gv_b,
                                           rel_table, gsb, alpha, bqp);

    // 5. output projection: [40960 x 512] @ Wo + bo
    {
        dim3 grid(Dd / 128, Mrows / 128);   // (4, 320)
        tc_gemm<0, true><<<grid, 256, GEMM_SMEM>>>(pah, pal, pwoh, pwol,
                                                   (float*)d_out, bo, Dd, Dd);
    }
}

// round 13
// speedup vs baseline: 1.3902x; 1.3249x over previous
#include <cuda_runtime.h>
#include <cuda_fp16.h>
#include <math.h>
#include <stdint.h>
#include <stddef.h>

// ------------ problem constants ------------
#define Bsz   2048
#define Nn    20
#define Dd    512
#define Hh    8
#define Mrows (Bsz*Nn)     // 40960
#define K3    (3*Dd)       // 1536

// ------------ scratch (static __device__) ------------
__device__ __align__(256) float g_conv[(size_t)Mrows * K3];     // conv GEMM out (fp32)
__device__ __align__(256) float g_qp[(size_t)Mrows * Hh];
__device__ __align__(256) float g_wqft[(size_t)64 * Dd];        // Wqf^T [c][i]
__device__ __align__(256) __half g_xf[(size_t)Mrows * Dd];      // x as fp16
__device__ __align__(256) __half g_af[(size_t)Mrows * Dd];      // attn out fp16
__device__ __align__(256) __half g_wth[(size_t)K3 * K3];        // W^T concat hi [oc][kk]
__device__ __align__(256) __half g_wtl[(size_t)K3 * K3];        // W^T concat lo
__device__ __align__(256) __half g_woh[(size_t)Dd * Dd];        // Wo^T hi [n][k]
__device__ __align__(256) __half g_wol[(size_t)Dd * Dd];        // Wo^T lo

// ------------ small PTX helpers (plain-sm_103-safe) ------------
__device__ __forceinline__ uint32_t smem_u32(const void* p) {
    uint32_t a;
    asm("{ .reg .u64 t; cvta.to.shared.u64 t, %1; cvt.u32.u64 %0, t; }" : "=r"(a) : "l"(p));
    return a;
}
__device__ __forceinline__ void cp_async16(uint32_t saddr, const void* gaddr, uint32_t srcsize) {
    asm volatile("cp.async.cg.shared.global [%0], [%1], 16, %2;"
                 :: "r"(saddr), "l"(gaddr), "r"(srcsize) : "memory");
}
__device__ __forceinline__ void cp_commit() { asm volatile("cp.async.commit_group;" ::: "memory"); }
__device__ __forceinline__ void cp_wait0()  { asm volatile("cp.async.wait_group 0;" ::: "memory"); }
__device__ __forceinline__ void cp_wait1()  { asm volatile("cp.async.wait_group 1;" ::: "memory"); }

__device__ __forceinline__ void ldsm4(uint32_t* r, uint32_t addr) {
    asm volatile("ldmatrix.sync.aligned.m8n8.x4.shared.b16 {%0,%1,%2,%3}, [%4];"
                 : "=r"(r[0]), "=r"(r[1]), "=r"(r[2]), "=r"(r[3]) : "r"(addr));
}
__device__ __forceinline__ void mma16816h(float* c, const uint32_t* a, const uint32_t* b) {
    asm volatile("mma.sync.aligned.m16n8k16.row.col.f32.f16.f16.f32 "
                 "{%0,%1,%2,%3}, {%4,%5,%6,%7}, {%8,%9}, {%0,%1,%2,%3};"
                 : "+f"(c[0]), "+f"(c[1]), "+f"(c[2]), "+f"(c[3])
                 : "r"(a[0]), "r"(a[1]), "r"(a[2]), "r"(a[3]), "r"(b[0]), "r"(b[1]));
}

// ============================================================
// precompute kernels
// ============================================================
__global__ void split_x(const float* __restrict__ x) {
    size_t i = (size_t)blockIdx.x * 256 + threadIdx.x;
    if (i >= (size_t)Mrows * Dd) return;
    g_xf[i] = __float2half(x[i]);
}

// Wt[oc][kk] = W_p[o, i, t], oc = p*512+o, kk = t*512+i  (fp16 hi/lo)
__global__ void repack_w(const float* __restrict__ Wq,
                         const float* __restrict__ Wk,
                         const float* __restrict__ Wv) {
    size_t idx = (size_t)blockIdx.x * 256 + threadIdx.x;
    if (idx >= (size_t)K3 * K3) return;
    int oc = (int)(idx / K3);
    int kk = (int)(idx - (size_t)oc * K3);
    int t = kk >> 9, i = kk & 511;
    int p = oc >> 9, o = oc & 511;
    const float* W = (p == 0) ? Wq : (p == 1) ? Wk : Wv;
    float v = W[(size_t)o * K3 + i * 3 + t];
    __half h = __float2half(v);
    g_wth[idx] = h;
    g_wtl[idx] = __float2half(v - __half2float(h));
}

__global__ void repack_wo(const float* __restrict__ Wo, const float* __restrict__ Wqf) {
    int idx = blockIdx.x * 256 + threadIdx.x;
    if (idx < 64 * Dd) {
        int c = idx >> 9, i = idx & 511;
        g_wqft[idx] = Wqf[(size_t)i * 64 + c];
    }
    if (idx >= Dd * Dd) return;
    int n = idx >> 9, k = idx & 511;
    float v = Wo[(size_t)k * Dd + n];
    __half h = __float2half(v);
    g_woh[idx] = h;
    g_wol[idx] = __float2half(v - __half2float(h));
}

// ============================================================
// fp16 2-pass GEMM: C = A * B^T (B stored [N x K], hi/lo fp16).
//   A single fp16 (activations), B = Bh + Bl (weights, exact).
//   C = A*Bh + A*Bl, fp32 accumulators.
// MODE 1: A gathered via im2col of x.
// CTA 128x128, 128 thr (4 warps 2x2), warp tile 64x64, BK=32,
// double buffer, prefetch before wait. __launch_bounds__(128,2).
// smem rows: 32 data + 8 pad = 40 halfs (80B) -> conflict-free.
// ============================================================
#define LDS_E 40
#define TILE_E (128 * LDS_E)
#define TILE_BYTES (TILE_E * 2)          // 10240 B
#define STAGE_BYTES (3 * TILE_BYTES)     // 30720 B (A, Bh, Bl)
#define GEMM_SMEM (2 * STAGE_BYTES)      // 61440 B

template<int MODE, bool BIAS>
__global__ __launch_bounds__(128, 2)
void tc_gemm(const __half* __restrict__ Af,
             const __half* __restrict__ Bh, const __half* __restrict__ Bl,
             float* __restrict__ C, const float* __restrict__ bias, int K, int N)
{
    extern __shared__ __half smem[];
    const uint32_t sb = smem_u32(smem);
    const int tid = threadIdx.x;
    const int wid = tid >> 5, lid = tid & 31;
    const int warp_m = wid >> 1;      // 0..1 (64 rows)
    const int warp_n = wid & 1;       // 0..1 (64 cols)
    const int m0 = blockIdx.y * 128, n0 = blockIdx.x * 128;
    const int NC = K >> 5;

    // stage loader: 3 tiles x 512 16B-chunks, 128 thr -> 12 chunks each
    auto load_stage = [&](int c) {
        const int buf = c & 1;
        const int kk0 = c << 5;
        uint32_t sbase = sb + (uint32_t)buf * STAGE_BYTES;
        #pragma unroll
        for (int it = 0; it < 4; it++) {
            int id = tid + it * 128;            // 0..511
            int r = id >> 2, q = id & 3;        // row, 16B quad
            uint32_t soff = (uint32_t)(r * LDS_E + q * 8) * 2;
            size_t aoff; uint32_t vsz = 16;
            if (MODE == 1) {
                int gm = m0 + r;
                int bb = gm / Nn, nn = gm - bb * Nn;
                int t = kk0 >> 9;
                int d = (kk0 & 511) + q * 8;
                int jj = nn + t - 1;
                if (jj < 0 || jj >= Nn) { vsz = 0; jj = 0; }
                aoff = ((size_t)(bb * Nn + jj) << 9) + d;
            } else {
                aoff = (size_t)(m0 + r) * K + kk0 + q * 8;
            }
            cp_async16(sbase + 0 * TILE_BYTES + soff, Af + aoff, vsz);
            size_t boff = (size_t)(n0 + r) * K + kk0 + q * 8;
            cp_async16(sbase + 1 * TILE_BYTES + soff, Bh + boff, 16);
            cp_async16(sbase + 2 * TILE_BYTES + soff, Bl + boff, 16);
        }
        cp_commit();
    };

    float acc[4][8][4];
    #pragma unroll
    for (int i = 0; i < 4; i++)
        #pragma unroll
        for (int j = 0; j < 8; j++)
            #pragma unroll
            for (int e = 0; e < 4; e++) acc[i][j][e] = 0.f;

    load_stage(0);

    // ldmatrix lane addressing (byte units within a [128][40] tile)
    const uint32_t a_row  = (uint32_t)(warp_m * 64 + (lid & 15));
    const uint32_t a_koff = (uint32_t)((lid >> 4) * 16);
    const uint32_t b_row  = (uint32_t)(warp_n * 64 + ((lid >> 4) * 8) + (lid & 7));
    const uint32_t b_koff = (uint32_t)(((lid >> 3) & 1) * 16);

    for (int c = 0; c < NC; c++) {
        if (c + 1 < NC) { load_stage(c + 1); cp_wait1(); }
        else            { cp_wait0(); }
        __syncthreads();

        const uint32_t sbase = sb + (uint32_t)(c & 1) * STAGE_BYTES;
        const uint32_t tA  = sbase + 0 * TILE_BYTES;
        const uint32_t tBh = sbase + 1 * TILE_BYTES;
        const uint32_t tBl = sbase + 2 * TILE_BYTES;

        #pragma unroll
        for (int ks = 0; ks < 2; ks++) {
            const uint32_t kb = (uint32_t)(ks * 32);
            uint32_t fbh[4][4], fbl[4][4];
            #pragma unroll
            for (int nb = 0; nb < 4; nb++) {
                uint32_t bo = ((b_row + nb * 16) * LDS_E) * 2 + b_koff + kb;
                ldsm4(fbh[nb], tBh + bo);
                ldsm4(fbl[nb], tBl + bo);
            }
            #pragma unroll
            for (int ma = 0; ma < 4; ma++) {
                uint32_t fa[4];
                uint32_t ao = ((a_row + ma * 16) * LDS_E) * 2 + a_koff + kb;
                ldsm4(fa, tA + ao);
                #pragma unroll
                for (int na = 0; na < 8; na++) {
                    const uint32_t* bh = &fbh[na >> 1][(na & 1) * 2];
                    const uint32_t* bl = &fbl[na >> 1][(na & 1) * 2];
                    mma16816h(acc[ma][na], fa, bh);
                    mma16816h(acc[ma][na], fa, bl);
                }
            }
        }
        __syncthreads();
    }

    // ---- epilogue ----
    const int mrow = m0 + warp_m * 64 + (lid >> 2);
    const int ncol = n0 + warp_n * 64 + (lid & 3) * 2;
    #pragma unroll
    for (int ma = 0; ma < 4; ma++) {
        #pragma unroll
        for (int na = 0; na < 8; na++) {
            int cc = ncol + na * 8;
            float b0 = 0.f, b1 = 0.f;
            if (BIAS) { b0 = bias[cc]; b1 = bias[cc + 1]; }
            float2 v0 = make_float2(acc[ma][na][0] + b0, acc[ma][na][1] + b1);
            float2 v1 = make_float2(acc[ma][na][2] + b0, acc[ma][na][3] + b1);
            *(float2*)(C + (size_t)(mrow + ma * 16)     * N + cc) = v0;
            *(float2*)(C + (size_t)(mrow + ma * 16 + 8) * N + cc) = v1;
        }
    }
}

// ============================================================
// qp[b,n,h] = tanh(x @ Wqf + bqf) @ Wqp  (dyn bias factorization)
// ============================================================
__global__ __launch_bounds__(256)
void qp_kernel(const float* __restrict__ x,
               const float* __restrict__ bqf, const float* __restrict__ Wqp)
{
    __shared__ float xs[32 * 513];
    __shared__ float qf[32 * 64];
    const int m0 = blockIdx.x * 32;
    const int tid = threadIdx.x;

    for (int u = tid; u < 32 * 128; u += 256) {
        int r = u >> 7, q = u & 127;
        float4 v = *(const float4*)(x + (size_t)(m0 + r) * Dd + q * 4);
        float* d = xs + r * 513 + q * 4;
        d[0] = v.x; d[1] = v.y; d[2] = v.z; d[3] = v.w;
    }
    __syncthreads();

    const int r  = tid & 31;
    const int cg = tid >> 5;
    float acc[8];
    #pragma unroll
    for (int j = 0; j < 8; j++) acc[j] = bqf[cg * 8 + j];

    const float* xr = xs + r * 513;
    for (int i = 0; i < 512; i += 4) {
        float x0 = xr[i], x1 = xr[i + 1], x2 = xr[i + 2], x3 = xr[i + 3];
        #pragma unroll
        for (int j = 0; j < 8; j++) {
            float4 w = *(const float4*)(g_wqft + (size_t)(cg * 8 + j) * Dd + i);
            acc[j] += x0 * w.x + x1 * w.y + x2 * w.z + x3 * w.w;
        }
    }
    #pragma unroll
    for (int j = 0; j < 8; j++) qf[r * 64 + cg * 8 + j] = tanhf(acc[j]);
    __syncthreads();

    const int r2 = tid >> 3, h = tid & 7;
    float a = 0.f;
    #pragma unroll
    for (int c = 0; c < 64; c++) a += qf[r2 * 64 + c] * Wqp[c * 8 + h];
    g_qp[(size_t)(m0 + r2) * 8 + h] = a;
}

// ============================================================
// Fused LN+residual + attention, one block per batch b.
// q,k slabs resident; v stats streaming; v overwrites dead q-slab.
// ~97KB smem -> 2 CTAs/SM.  Emits fp16 attn output.
// ============================================================
#define LNROW 513
#define SM2_SC   (2 * Nn * LNROW)
#define SM2_REL  (SM2_SC + Hh * Nn * Nn)
#define SM2_QPH  (SM2_REL + Hh * (2 * Nn - 1))
#define SM2_VM   (SM2_QPH + Nn * Hh)
#define SM2_VR   (SM2_VM + Nn)
#define FUSED2_F (SM2_VR + Nn)
#define FUSED2_B (FUSED2_F * 4)

__global__ __launch_bounds__(512, 2)
void ln_attn_kernel(const float* __restrict__ xin,
                    const float* __restrict__ gq_g, const float* __restrict__ gq_b,
                    const float* __restrict__ gk_g, const float* __restrict__ gk_b,
                    const float* __restrict__ gv_g, const float* __restrict__ gv_b,
                    const float* __restrict__ rel_table,
                    const float* __restrict__ gsb,
                    const float* __restrict__ alpha_p,
                    const float* __restrict__ bqp)
{
    extern __shared__ float sm[];
    float* buf   = sm;                 // [2][20][513]  q,k  (later: slab0 = v)
    float* sc    = sm + SM2_SC;
    float* relh  = sm + SM2_REL;
    float* qph   = sm + SM2_QPH;
    float* vmean = sm + SM2_VM;
    float* vrstd = sm + SM2_VR;

    const int b = blockIdx.x;
    const int tid = threadIdx.x;
    const int wid = tid >> 5, lid = tid & 31;

    for (int i = tid; i < 2 * Nn * Dd; i += 512) {
        int p = i / (Nn * Dd);
        int rem = i - p * Nn * Dd;
        int n = rem >> 9, d = rem & 511;
        buf[(p * Nn + n) * LNROW + d] =
            g_conv[(size_t)(b * Nn + n) * K3 + p * Dd + d];
    }
    if (tid < Hh * (2 * Nn - 1)) relh[tid] = rel_table[(tid % (2 * Nn - 1)) * Hh + (tid / (2 * Nn - 1))];
    else if (tid >= 480 && tid < 480 + Nn) {
        int n = tid - 480;
        #pragma unroll
        for (int h = 0; h < Hh; h++)
            qph[n * Hh + h] = g_qp[(size_t)(b * Nn + n) * Hh + h];
    }

    for (int r = wid; r < Nn; r += 16) {
        const float* vr = g_conv + (size_t)(b * Nn + r) * K3 + 2 * Dd;
        float s = 0.f, sq = 0.f;
        #pragma unroll
        for (int j = 0; j < 16; j++) {
            float v = vr[lid + j * 32];
            s += v; sq += v * v;
        }
        #pragma unroll
        for (int o = 16; o > 0; o >>= 1) {
            s  += __shfl_xor_sync(0xffffffffu, s,  o);
            sq += __shfl_xor_sync(0xffffffffu, sq, o);
        }
        if (lid == 0) {
            float mean = s * (1.f / 512.f);
            float var  = sq * (1.f / 512.f) - mean * mean;
            vmean[r] = mean;
            vrstd[r] = rsqrtf(var + 1e-5f);
        }
    }
    __syncthreads();

    for (int r = wid; r < 2 * Nn; r += 16) {
        int p = r / Nn, n = r - p * Nn;
        float* row = buf + r * LNROW;
        float s = 0.f, sq = 0.f;
        #pragma unroll
        for (int j = 0; j < 16; j++) {
            float v = row[lid + j * 32];
            s += v; sq += v * v;
        }
        #pragma unroll
        for (int o = 16; o > 0; o >>= 1) {
            s  += __shfl_xor_sync(0xffffffffu, s,  o);
            sq += __shfl_xor_sync(0xffffffffu, sq, o);
        }
        float mean = s * (1.f / 512.f);
        float var  = sq * (1.f / 512.f) - mean * mean;
        float rstd = rsqrtf(var + 1e-5f);
        const float* g  = (p == 0) ? gq_g : gk_g;
        const float* be = (p == 0) ? gq_b : gk_b;
        const float* xr = xin + (size_t)(b * Nn + n) * Dd;
        #pragma unroll
        for (int j = 0; j < 16; j++) {
            int d = lid + j * 32;
            row[d] = xr[d] + (row[d] - mean) * rstd * g[d] + be[d];
        }
    }
    __syncthreads();

    const float alpha = *alpha_p;
    const float* q = buf;
    const float* k = buf + Nn * LNROW;
    for (int t = tid; t < Hh * Nn * Nn; t += 512) {
        int h = t / (Nn * Nn);
        int rem = t - h * Nn * Nn;
        int n = rem / Nn, m = rem - n * Nn;
        const float* qr = q + n * LNROW + h * 64;
        const float* kr = k + m * LNROW + h * 64;
        float a = 0.f;
        #pragma unroll
        for (int d = 0; d < 64; d++) a += qr[d] * kr[d];
        a = a * 0.125f
          + relh[h * (2 * Nn - 1) + n - m + Nn - 1]
          + alpha * gsb[(size_t)(h * Nn + n) * Nn + m]
          + (qph[n * Hh + h] - qph[m * Hh + h]) + bqp[h];
        sc[t] = a;
    }
    __syncthreads();

    if (tid < Hh * Nn) {
        float* row = sc + tid * Nn;
        float mx = -1e30f;
        #pragma unroll
        for (int m = 0; m < Nn; m++) mx = fmaxf(mx, row[m]);
        float s = 0.f;
        #pragma unroll
        for (int m = 0; m < Nn; m++) { float e = expf(row[m] - mx); row[m] = e; s += e; }
        float inv = 1.f / s;
        #pragma unroll
        for (int m = 0; m < Nn; m++) row[m] *= inv;
    }
    __syncthreads();

    for (int i = tid; i < Nn * Dd; i += 512) {
        int n = i >> 9, d = i & 511;
        float cv = g_conv[(size_t)(b * Nn + n) * K3 + 2 * Dd + d];
        float val = xin[(size_t)(b * Nn + n) * Dd + d]
                  + (cv - vmean[n]) * vrstd[n] * gv_g[d] + gv_b[d];
        buf[n * LNROW + d] = val;
    }
    __syncthreads();

    const float* v = buf;
    for (int t = tid; t < Hh * Nn * 64; t += 512) {
        int hn = t >> 6, d = t & 63;
        int h = hn / Nn, n = hn - h * Nn;
        const float* ar = sc + (h * Nn + n) * Nn;
        const float* vb = v + h * 64 + d;
        float a = 0.f;
        #pragma unroll
        for (int m = 0; m < Nn; m++) a += ar[m] * vb[m * LNROW];
        g_af[(size_t)(b * Nn + n) * Dd + h * 64 + d] = __float2half(a);
    }
}

// ============================================================
// launch
// ============================================================
extern "C" void kernel_launch(void* const* d_in, const int* in_sizes, int n_in,
                              void* d_out, int out_size)
{
    const float* x         = (const float*)d_in[0];
    const float* Wq        = (const float*)d_in[1];
    const float* Wk        = (const float*)d_in[2];
    const float* Wv        = (const float*)d_in[3];
    const float* gq_g      = (const float*)d_in[4];
    const float* gq_b      = (const float*)d_in[5];
    const float* gk_g      = (const float*)d_in[6];
    const float* gk_b      = (const float*)d_in[7];
    const float* gv_g      = (const float*)d_in[8];
    const float* gv_b      = (const float*)d_in[9];
    const float* rel_table = (const float*)d_in[10];
    const float* gsb       = (const float*)d_in[11];
    const float* alpha     = (const float*)d_in[12];
    const float* Wqf       = (const float*)d_in[13];
    const float* bqf       = (const float*)d_in[14];
    const float* Wqp       = (const float*)d_in[15];
    const float* bqp       = (const float*)d_in[16];
    const float* Wo        = (const float*)d_in[17];
    const float* bo        = (const float*)d_in[18];

    cudaFuncSetAttribute(tc_gemm<1, false>, cudaFuncAttributeMaxDynamicSharedMemorySize, GEMM_SMEM);
    cudaFuncSetAttribute(tc_gemm<0, true>,  cudaFuncAttributeMaxDynamicSharedMemorySize, GEMM_SMEM);
    cudaFuncSetAttribute(ln_attn_kernel,    cudaFuncAttributeMaxDynamicSharedMemorySize, FUSED2_B);

    __half *pxf, *paf, *pwth, *pwtl, *pwoh, *pwol;
    float *pConv;
    cudaGetSymbolAddress((void**)&pxf, g_xf);
    cudaGetSymbolAddress((void**)&paf, g_af);
    cudaGetSymbolAddress((void**)&pwth, g_wth);
    cudaGetSymbolAddress((void**)&pwtl, g_wtl);
    cudaGetSymbolAddress((void**)&pwoh, g_woh);
    cudaGetSymbolAddress((void**)&pwol, g_wol);
    cudaGetSymbolAddress((void**)&pConv, g_conv);

    // 1. precompute fp16 conversions / weight splits
    split_x<<<(Mrows * Dd + 255) / 256, 256>>>(x);
    repack_w<<<(K3 * K3 + 255) / 256, 256>>>(Wq, Wk, Wv);
    repack_wo<<<(Dd * Dd + 255) / 256, 256>>>(Wo, Wqf);

    // 2. fused QKV conv as im2col GEMM: [40960 x 1536]
    {
        dim3 grid(K3 / 128, Mrows / 128);   // (12, 320)
        tc_gemm<1, false><<<grid, 128, GEMM_SMEM>>>(pxf, pwth, pwtl,
                                                    pConv, nullptr, K3, K3);
    }

    // 3. dynamic-bias projection qp
    qp_kernel<<<Mrows / 32, 256>>>(x, bqf, Wqp);

    // 4. fused LN+residual + attention (per batch), emits fp16
    ln_attn_kernel<<<Bsz, 512, FUSED2_B>>>(x, gq_g, gq_b, gk_g, gk_b, gv_g, gv_b,
                                           rel_table, gsb, alpha, bqp);

    // 5. output projection: [40960 x 512] @ Wo + bo
    {
        dim3 grid(Dd / 128, Mrows / 128);   // (4, 320)
        tc_gemm<0, true><<<grid, 128, GEMM_SMEM>>>(paf, pwoh, pwol,
                                                   (float*)d_out, bo, Dd, Dd);
    }
}